// round 16
// baseline (speedup 1.0000x reference)
#include <cuda_runtime.h>
#include <math.h>

// YOLOv1 loss — persistent 6-deep cp.async pipeline.
// R15 (double buffer, 2-sample tiles) measured stage-limited at 3.16TB/s with
// 94KB/SM in flight; R7A reached 4.35TB/s at ~150-230KB/SM. BW tracks
// outstanding bytes, so: 1-sample tiles (11.76KB), DEPTH=6, 3 CTAs/SM ->
// ~176KB/SM pending. 1-sample tile bases are 8B-aligned -> 8-byte cp.async.ca.
//
// Exactness: max_iou is only ever compared against 0, and union>0 always
// (w,h >= 0.05), so cmask == "exists masked pred box with intersection > 0".
// The intersection arithmetic (cx - 0.5f*w, min/max/sub, >0 test) matches the
// reference ops exactly, so the decision is bit-identical.
//
// Graph-replay invariants: g_partCTA[0..ncta) fully overwritten each run;
// g_count is 0 at every launch start (reset by the last CTA after use).

#define CELLS 49
#define CH 30
#define FPS (CELLS * CH)          // 1470 floats per sample
#define TPB 128                   // 4 warps
#define DEPTH 6                   // pipeline stages (buffers)
#define NCTA_MAX 444              // 148 SMs x 3 resident

__device__ __align__(16) float4 g_partCTA[NCTA_MAX];
__device__ unsigned int g_count = 0;

__global__ __launch_bounds__(TPB) void yolo_deep_kernel(
    const float* __restrict__ pred, const float* __restrict__ target,
    float* __restrict__ out, int B, int ncta)
{
    // each buffer: pred sample [0,1470) | target sample [1470,2940)
    __shared__ __align__(16) float sbuf[DEPTH][2 * FPS];
    __shared__ int s_list[CELLS];
    __shared__ float4 s_red[4];
    __shared__ int s_last;

    const int tid  = threadIdx.x;
    const int lane = tid & 31;
    const int w    = tid >> 5;
    const int t0   = blockIdx.x;

    float noobj = 0.f, cls = 0.f, coord = 0.f, objc = 0.f;

    // ---- stage sample t into buffer bi (8B cp.async; empty-commit if t>=B) ----
    auto stage = [&](int t, int bi) {
        if (t < B) {
            const float2* gp = (const float2*)(pred + (size_t)t * FPS);   // 8B aligned
            const float2* gt = (const float2*)(target + (size_t)t * FPS);
            const unsigned sb = (unsigned)__cvta_generic_to_shared(sbuf[bi]);
            for (int i = tid; i < FPS / 2; i += TPB) {                    // 735 units
                asm volatile("cp.async.ca.shared.global [%0], [%1], 8;\n"
                             :: "r"(sb + 8u * i), "l"(gp + i) : "memory");
                asm volatile("cp.async.ca.shared.global [%0], [%1], 8;\n"
                             :: "r"(sb + 4u * (unsigned)FPS + 8u * i), "l"(gt + i)
                             : "memory");
            }
        }
        asm volatile("cp.async.commit_group;\n" ::: "memory");
    };

    // ---- prologue: fill DEPTH-1 stages ----
    #pragma unroll
    for (int j = 0; j < DEPTH - 1; j++)
        stage(t0 + j * ncta, j);

    for (int t = t0, k = 0; t < B; t += ncta, k++) {
        stage(t + (DEPTH - 1) * ncta, (k + DEPTH - 1) % DEPTH);
        asm volatile("cp.async.wait_group %0;\n" :: "n"(DEPTH - 1) : "memory");
        __syncthreads();                          // tile t fully staged (all threads)

        // ---- compute sample t: warp (k&3) owns it ----
        if (w == (k & 3)) {
            const float* ps = sbuf[k % DEPTH];
            const float* ts = sbuf[k % DEPTH] + FPS;

            int nobj = 0;
            #pragma unroll
            for (int half = 0; half < 2; half++) {
                const int c = lane + 32 * half;
                bool isobj = false;
                if (c < CELLS) {
                    const float* pc = ps + c * CH;
                    const float* tc = ts + c * CH;
                    if (tc[4] == 0.f) {           // conf exactly 0/1
                        const float d4 = pc[4] - tc[4];
                        const float d9 = pc[9] - tc[9];
                        noobj += d4 * d4 + d9 * d9;
                    } else {
                        isobj = true;
                        float acc = 0.f;
                        #pragma unroll
                        for (int kk = 10; kk < CH; kk++) {
                            const float d = pc[kk] - tc[kk];
                            acc += d * d;
                        }
                        cls += acc;
                    }
                }
                const unsigned m = __ballot_sync(0xffffffffu, isobj);
                if (isobj)
                    s_list[nobj + __popc(m & ((1u << lane) - 1u))] = c;
                nobj += __popc(m);
            }
            __syncwarp();

            const int nbox = 2 * nobj;
            for (int i = lane; i < nbox; i += 32) {
                const int toff = s_list[i >> 1] * CH + 5 * (i & 1);
                const float* tb = ts + toff;
                const float tcx = tb[0], tcy = tb[1], tw = tb[2], th = tb[3];
                const float tx0 = tcx - 0.5f * tw, ty0 = tcy - 0.5f * th;
                const float tx1 = tcx + 0.5f * tw, ty1 = tcy + 0.5f * th;

                bool found = false;
                for (int j = 0; j < nbox; j++) {  // j uniform -> LDS broadcast
                    const int po = s_list[j >> 1] * CH + 5 * (j & 1);
                    const float pcx = ps[po],     pcy = ps[po + 1];
                    const float pw  = ps[po + 2], ph  = ps[po + 3];
                    const float ix = fminf(pcx + 0.5f * pw, tx1) - fmaxf(pcx - 0.5f * pw, tx0);
                    const float iy = fminf(pcy + 0.5f * ph, ty1) - fmaxf(pcy - 0.5f * ph, ty0);
                    if (ix > 0.f && iy > 0.f && ix * iy > 0.f) { found = true; break; }
                }
                if (found) {
                    const float* pb = ps + toff;
                    const float dx = pb[0] - tcx;
                    const float dy = pb[1] - tcy;
                    const float dw = sqrtf(pb[2]) - sqrtf(tw);
                    const float dh = sqrtf(pb[3]) - sqrtf(th);
                    coord += dx * dx + dy * dy + dw * dw + dh * dh;
                    const float dc = pb[4] - tb[4];
                    objc += dc * dc;
                }
            }
        }
        __syncthreads();                          // compute done before buffer reuse
    }

    // ---- warp reduce, CTA combine, last-CTA finish ----
    #pragma unroll
    for (int o = 16; o > 0; o >>= 1) {
        noobj += __shfl_down_sync(0xffffffffu, noobj, o);
        cls   += __shfl_down_sync(0xffffffffu, cls, o);
        coord += __shfl_down_sync(0xffffffffu, coord, o);
        objc  += __shfl_down_sync(0xffffffffu, objc, o);
    }
    if (lane == 0)
        s_red[w] = make_float4(noobj, cls, coord, objc);
    __syncthreads();

    if (tid == 0) {
        float4 r = s_red[0];
        #pragma unroll
        for (int k = 1; k < 4; k++) {
            r.x += s_red[k].x; r.y += s_red[k].y;
            r.z += s_red[k].z; r.w += s_red[k].w;
        }
        g_partCTA[blockIdx.x] = r;
        __threadfence();
        const unsigned int old = atomicAdd(&g_count, 1u);
        s_last = (old == (unsigned int)(ncta - 1)) ? 1 : 0;
    }
    __syncthreads();

    if (!s_last) return;

    double a0 = 0.0, a1 = 0.0, a2 = 0.0, a3 = 0.0;
    for (int i = tid; i < ncta; i += TPB) {
        const float4 v = g_partCTA[i];
        a0 += (double)v.x;
        a1 += (double)v.y;
        a2 += (double)v.z;
        a3 += (double)v.w;
    }
    #pragma unroll
    for (int o = 16; o > 0; o >>= 1) {
        a0 += __shfl_down_sync(0xffffffffu, a0, o);
        a1 += __shfl_down_sync(0xffffffffu, a1, o);
        a2 += __shfl_down_sync(0xffffffffu, a2, o);
        a3 += __shfl_down_sync(0xffffffffu, a3, o);
    }
    __shared__ double sd[4][4];
    if (lane == 0) { sd[0][w] = a0; sd[1][w] = a1; sd[2][w] = a2; sd[3][w] = a3; }
    __syncthreads();
    if (tid == 0) {
        double r0 = 0, r1 = 0, r2 = 0, r3 = 0;
        #pragma unroll
        for (int k = 0; k < 4; k++) {
            r0 += sd[0][k]; r1 += sd[1][k]; r2 += sd[2][k]; r3 += sd[3][k];
        }
        const double inv = 1.0 / (double)B;
        const double cls_l = r1 * inv;
        const double obj_l = (r3 + 0.5 * r0) * inv;
        const double crd_l = r2 * 5.0 * inv;
        out[0] = (float)(cls_l + obj_l + crd_l);
        out[1] = (float)cls_l;
        out[2] = (float)obj_l;
        out[3] = (float)crd_l;
        g_count = 0u;                             // restore replay invariant
    }
}

extern "C" void kernel_launch(void* const* d_in, const int* in_sizes, int n_in,
                              void* d_out, int out_size)
{
    const float* pred = (const float*)d_in[0];
    const float* target = (const float*)d_in[1];
    const int B = in_sizes[0] / FPS;
    const int ncta = (B < NCTA_MAX) ? B : NCTA_MAX;

    yolo_deep_kernel<<<ncta, TPB>>>(pred, target, (float*)d_out, B, ncta);
}

// round 17
// speedup vs baseline: 1.1891x; 1.1891x over previous
#include <cuda_runtime.h>
#include <math.h>

// YOLOv1 loss — fused kernel on R7A's staging engine.
// Measured staging ranking: plain LDG.128->STS @ 92% occ = 4.35TB/s (R7A)
// >> cp.async 16B @ 23% occ = 2.9-3.2TB/s >> cp.async 8B = 1.9TB/s.
// So: 2-sample CTAs (16B-aligned bases), 256 threads, 23.5KB smem, float4
// LDG staging, __launch_bounds__(256,8) to keep regs<=32 for 8 CTAs/SM.
// Compute = proven warp-per-sample phase1/pairing (warps 0,1), then the
// proven last-CTA finish. Any register spills hit only the compute tail.
//
// Exactness: max_iou is only ever compared against 0, and union>0 always
// (w,h >= 0.05), so cmask == "exists masked pred box with intersection > 0".
// The intersection arithmetic (cx - 0.5f*w, min/max/sub, >0 test) matches the
// reference ops exactly, so the decision is bit-identical.
//
// Graph-replay invariants: g_partCTA[0..ncta) fully overwritten each run;
// g_count is 0 at every launch start (reset by the last CTA after use).

#define CELLS 49
#define CH 30
#define FPS (CELLS * CH)          // 1470 floats per sample
#define SPC 2                     // samples per CTA (16B-aligned chunk: 11760B)
#define TPB 256                   // 8 warps; warps 0,1 compute
#define MAXB 8192
#define MAXCTA ((MAXB + SPC - 1) / SPC)

__device__ __align__(16) float4 g_partCTA[MAXCTA];
__device__ unsigned int g_count = 0;

__global__ __launch_bounds__(TPB, 8) void yolo_fused_kernel(
    const float* __restrict__ pred, const float* __restrict__ target,
    float* __restrict__ out, int B, int total_floats, int ncta)
{
    __shared__ __align__(16) float sp[SPC * FPS];   // 2940 floats (both samples' pred)
    __shared__ __align__(16) float st[SPC * FPS];
    __shared__ int s_list[SPC][CELLS];
    __shared__ float4 s_red[TPB / 32];
    __shared__ int s_last;

    const int tid  = threadIdx.x;
    const int lane = tid & 31;
    const int w    = tid >> 5;
    const int f0   = blockIdx.x * (SPC * FPS);      // 11760B stride -> 16B aligned
    const int flen = min(SPC * FPS, total_floats - f0);

    // ---- staging: R7A idiom — plain float4 LDG -> STS, high occupancy ----
    {
        const int nv4 = flen >> 2;                  // 735 float4 per tensor
        const float4* gp4 = (const float4*)(pred + f0);
        const float4* gt4 = (const float4*)(target + f0);
        float4* sp4 = (float4*)sp;
        float4* st4 = (float4*)st;
        #pragma unroll 3
        for (int i = tid; i < nv4; i += TPB) {
            sp4[i] = gp4[i];
            st4[i] = gt4[i];
        }
        for (int i = (nv4 << 2) + tid; i < flen; i += TPB) {  // partial tail CTA
            sp[i] = pred[f0 + i];
            st[i] = target[f0 + i];
        }
    }
    __syncthreads();

    const int s = blockIdx.x * SPC + w;             // warps 0,1 own the samples
    float noobj = 0.f, cls = 0.f, coord = 0.f, objc = 0.f;

    if (w < SPC && s < B) {
        const float* ps = sp + w * FPS;
        const float* ts = st + w * FPS;

        // ---- phase 1: per-cell terms + ballot compaction of obj cells ----
        int nobj = 0;
        #pragma unroll
        for (int half = 0; half < 2; half++) {
            const int c = lane + 32 * half;
            bool isobj = false;
            if (c < CELLS) {
                const float* pc = ps + c * CH;
                const float* tc = ts + c * CH;
                if (tc[4] == 0.f) {                 // conf channel exactly 0/1
                    const float d4 = pc[4] - tc[4];
                    const float d9 = pc[9] - tc[9];
                    noobj += d4 * d4 + d9 * d9;
                } else {
                    isobj = true;
                    float acc = 0.f;
                    #pragma unroll
                    for (int k = 10; k < CH; k++) {
                        const float d = pc[k] - tc[k];
                        acc += d * d;
                    }
                    cls += acc;
                }
            }
            const unsigned m = __ballot_sync(0xffffffffu, isobj);
            if (isobj)
                s_list[w][nobj + __popc(m & ((1u << lane) - 1u))] = c;
            nobj += __popc(m);
        }
        __syncwarp();

        // ---- phase 2: in-warp pairing (existence test with early exit) ----
        const int nbox = 2 * nobj;
        for (int i = lane; i < nbox; i += 32) {
            const int toff = s_list[w][i >> 1] * CH + 5 * (i & 1);
            const float* tb = ts + toff;
            const float tcx = tb[0], tcy = tb[1], tw = tb[2], th = tb[3];
            const float tx0 = tcx - 0.5f * tw, ty0 = tcy - 0.5f * th;
            const float tx1 = tcx + 0.5f * tw, ty1 = tcy + 0.5f * th;

            bool found = false;
            for (int j = 0; j < nbox; j++) {        // j uniform -> LDS broadcast
                const int po = s_list[w][j >> 1] * CH + 5 * (j & 1);
                const float pcx = ps[po],     pcy = ps[po + 1];
                const float pw  = ps[po + 2], ph  = ps[po + 3];
                const float ix = fminf(pcx + 0.5f * pw, tx1) - fmaxf(pcx - 0.5f * pw, tx0);
                const float iy = fminf(pcy + 0.5f * ph, ty1) - fmaxf(pcy - 0.5f * ph, ty0);
                if (ix > 0.f && iy > 0.f && ix * iy > 0.f) { found = true; break; }
            }
            if (found) {
                const float* pb = ps + toff;
                const float dx = pb[0] - tcx;
                const float dy = pb[1] - tcy;
                const float dw = sqrtf(pb[2]) - sqrtf(tw);
                const float dh = sqrtf(pb[3]) - sqrtf(th);
                coord += dx * dx + dy * dy + dw * dw + dh * dh;
                const float dc = pb[4] - tb[4];
                objc += dc * dc;
            }
        }
    }

    // ---- warp reduce, CTA combine, last-CTA finish ----
    #pragma unroll
    for (int o = 16; o > 0; o >>= 1) {
        noobj += __shfl_down_sync(0xffffffffu, noobj, o);
        cls   += __shfl_down_sync(0xffffffffu, cls, o);
        coord += __shfl_down_sync(0xffffffffu, coord, o);
        objc  += __shfl_down_sync(0xffffffffu, objc, o);
    }
    if (lane == 0)
        s_red[w] = make_float4(noobj, cls, coord, objc);
    __syncthreads();

    if (tid == 0) {
        float4 r = s_red[0];
        #pragma unroll
        for (int k = 1; k < TPB / 32; k++) {
            r.x += s_red[k].x; r.y += s_red[k].y;
            r.z += s_red[k].z; r.w += s_red[k].w;
        }
        g_partCTA[blockIdx.x] = r;
        __threadfence();
        const unsigned int old = atomicAdd(&g_count, 1u);
        s_last = (old == (unsigned int)(ncta - 1)) ? 1 : 0;
    }
    __syncthreads();

    if (!s_last) return;

    // ---- last CTA: final reduction over ncta float4 (L2-hot, fixed order) ----
    double a0 = 0.0, a1 = 0.0, a2 = 0.0, a3 = 0.0;
    for (int i = tid; i < ncta; i += TPB) {
        const float4 v = g_partCTA[i];
        a0 += (double)v.x;
        a1 += (double)v.y;
        a2 += (double)v.z;
        a3 += (double)v.w;
    }
    #pragma unroll
    for (int o = 16; o > 0; o >>= 1) {
        a0 += __shfl_down_sync(0xffffffffu, a0, o);
        a1 += __shfl_down_sync(0xffffffffu, a1, o);
        a2 += __shfl_down_sync(0xffffffffu, a2, o);
        a3 += __shfl_down_sync(0xffffffffu, a3, o);
    }
    __shared__ double sd[4][TPB / 32];
    if (lane == 0) { sd[0][w] = a0; sd[1][w] = a1; sd[2][w] = a2; sd[3][w] = a3; }
    __syncthreads();
    if (tid == 0) {
        double r0 = 0, r1 = 0, r2 = 0, r3 = 0;
        #pragma unroll
        for (int k = 0; k < TPB / 32; k++) {
            r0 += sd[0][k]; r1 += sd[1][k]; r2 += sd[2][k]; r3 += sd[3][k];
        }
        const double inv = 1.0 / (double)B;
        const double cls_l = r1 * inv;
        const double obj_l = (r3 + 0.5 * r0) * inv;
        const double crd_l = r2 * 5.0 * inv;
        out[0] = (float)(cls_l + obj_l + crd_l);
        out[1] = (float)cls_l;
        out[2] = (float)obj_l;
        out[3] = (float)crd_l;
        g_count = 0u;                               // restore replay invariant
    }
}

extern "C" void kernel_launch(void* const* d_in, const int* in_sizes, int n_in,
                              void* d_out, int out_size)
{
    const float* pred = (const float*)d_in[0];
    const float* target = (const float*)d_in[1];
    const int B = in_sizes[0] / FPS;
    const int total_floats = B * FPS;
    const int ncta = (B + SPC - 1) / SPC;

    yolo_fused_kernel<<<ncta, TPB>>>(pred, target, (float*)d_out, B, total_floats, ncta);
}